// round 4
// baseline (speedup 1.0000x reference)
#include <cuda_runtime.h>
#include <cuda_bf16.h>
#include <cstdint>

#define NEXP 64
#define KDIM 1024
#define NROWS 131072
#define HIGH_NEG -100000.0f
#define CRANK0 98303u

// ---------------- scratch ----------------
#define NBINS 8192               // 13-bit level-1 histogram
#define CAP 8192                 // candidate capacity per expert
__device__ uint32_t g_hist1[NEXP * NBINS];
__device__ uint32_t g_cand[NEXP * CAP];
__device__ uint32_t g_cnt[NEXP];
__device__ uint32_t g_minb1[NEXP];
__device__ uint32_t g_bkt0[NEXP], g_rnk0[NEXP], g_bkt1[NEXP], g_rnk1[NEXP];
__device__ float    g_tcol[NEXP];
__device__ __nv_bfloat16 g_whi[NEXP * KDIM];
__device__ __nv_bfloat16 g_wlo[NEXP * KDIM];

// ---------------- helpers ----------------
__device__ __forceinline__ uint32_t f2o(float f) {
    uint32_t u = __float_as_uint(f);
    return u ^ ((u & 0x80000000u) ? 0xFFFFFFFFu : 0x80000000u);
}
__device__ __forceinline__ float o2f(uint32_t u) {
    u ^= ((u & 0x80000000u) ? 0x80000000u : 0xFFFFFFFFu);
    return __uint_as_float(u);
}
__device__ __forceinline__ uint32_t smem_u32(const void* p) {
    uint32_t a;
    asm("{ .reg .u64 t; cvta.to.shared.u64 t, %1; cvt.u32.u64 %0, t; }" : "=r"(a) : "l"(p));
    return a;
}
__device__ __forceinline__ void ldmx4(uint32_t* r, uint32_t addr) {
    asm volatile("ldmatrix.sync.aligned.m8n8.x4.shared.b16 {%0,%1,%2,%3}, [%4];"
                 : "=r"(r[0]), "=r"(r[1]), "=r"(r[2]), "=r"(r[3]) : "r"(addr));
}
__device__ __forceinline__ void mma_bf16(float* d, const uint32_t* a,
                                         uint32_t b0, uint32_t b1) {
    asm volatile(
        "mma.sync.aligned.m16n8k16.row.col.f32.bf16.bf16.f32 "
        "{%0,%1,%2,%3}, {%4,%5,%6,%7}, {%8,%9}, {%0,%1,%2,%3};"
        : "+f"(d[0]), "+f"(d[1]), "+f"(d[2]), "+f"(d[3])
        : "r"(a[0]), "r"(a[1]), "r"(a[2]), "r"(a[3]), "r"(b0), "r"(b1));
}
__device__ __forceinline__ uint32_t warp_iscan(uint32_t v, int lane) {
#pragma unroll
    for (int o = 1; o < 32; o <<= 1) {
        uint32_t t = __shfl_up_sync(0xffffffffu, v, o);
        if (lane >= o) v += t;
    }
    return v;
}

// ---------------- launch index 0: zero hist1 ----------------
__global__ void zero_hist1() {
    uint4* a = reinterpret_cast<uint4*>(g_hist1);
    int i = blockIdx.x * blockDim.x + threadIdx.x;   // grid covers exactly
    a[i] = make_uint4(0u, 0u, 0u, 0u);
}

// ---------------- launch index 1: W -> bf16 hi/lo ----------------
__global__ void w_convert(const float* __restrict__ W) {
    int i = blockIdx.x * blockDim.x + threadIdx.x;
    float v = W[i];
    __nv_bfloat16 h = __float2bfloat16(v);
    g_whi[i] = h;
    g_wlo[i] = __float2bfloat16(v - __bfloat162float(h));
}

// ---------------- launch index 2: small inits (also pads profile slot) -------
__global__ void init_small() {
    if (threadIdx.x < NEXP) {
        g_cnt[threadIdx.x] = 0u;
        g_minb1[threadIdx.x] = 0xFFFFFFFFu;
    }
}

// ---------------- launch index 3: double-buffered mma GEMM -------------------
#define BM 128
#define CHUNK 64
#define NCH (KDIM / CHUNK)
#define SM_A_HI 0
#define SM_A_LO 18432
#define SM_B_HI 36864
#define SM_B_LO 46080
#define BUF_SZ 55296
#define SMEM_TOTAL (2 * BUF_SZ)
#define STG 68

__device__ __forceinline__ void stage_chunk(char* smem, int buf, const float4* xb,
                                            int tid, int kc) {
    char* aH = smem + buf * BUF_SZ + SM_A_HI;
    char* aL = smem + buf * BUF_SZ + SM_A_LO;
    char* bH = smem + buf * BUF_SZ + SM_B_HI;
    char* bL = smem + buf * BUF_SZ + SM_B_LO;
#pragma unroll
    for (int i = 0; i < 8; i++) {
        int l = tid + i * 256;
        int r = l >> 4, q = l & 15;
        float4 v = xb[i];
        uint32_t h01, h23, l01, l23;
        asm("cvt.rn.bf16x2.f32 %0, %1, %2;" : "=r"(h01) : "f"(v.y), "f"(v.x));
        asm("cvt.rn.bf16x2.f32 %0, %1, %2;" : "=r"(h23) : "f"(v.w), "f"(v.z));
        float r0 = v.x - __uint_as_float(h01 << 16);
        float r1 = v.y - __uint_as_float(h01 & 0xFFFF0000u);
        float r2 = v.z - __uint_as_float(h23 << 16);
        float r3 = v.w - __uint_as_float(h23 & 0xFFFF0000u);
        asm("cvt.rn.bf16x2.f32 %0, %1, %2;" : "=r"(l01) : "f"(r1), "f"(r0));
        asm("cvt.rn.bf16x2.f32 %0, %1, %2;" : "=r"(l23) : "f"(r3), "f"(r2));
        uint32_t off = (uint32_t)(r * 144 + q * 8);
        *reinterpret_cast<uint2*>(aH + off) = make_uint2(h01, h23);
        *reinterpret_cast<uint2*>(aL + off) = make_uint2(l01, l23);
    }
    const uint4* wh = reinterpret_cast<const uint4*>(g_whi);
    const uint4* wl = reinterpret_cast<const uint4*>(g_wlo);
#pragma unroll
    for (int i = 0; i < 2; i++) {
        int l = tid + i * 256;
        int e = l >> 3, q = l & 7;
        uint32_t src = (uint32_t)(e * KDIM + kc) >> 3;
        uint32_t off = (uint32_t)(e * 144 + q * 16);
        *reinterpret_cast<uint4*>(bH + off) = wh[src + q];
        *reinterpret_cast<uint4*>(bL + off) = wl[src + q];
    }
}

__global__ __launch_bounds__(256, 2) void gemm_mma(
    const float* __restrict__ x, const float* __restrict__ bias,
    const float* __restrict__ noise, float* __restrict__ out)
{
    extern __shared__ char smem[];
    const uint32_t sb = smem_u32(smem);
    const int tid = threadIdx.x;
    const int wid = tid >> 5, lid = tid & 31;
    const int wm = wid >> 2, wn = wid & 3;
    const int rowBase = blockIdx.x * BM;
    const float* xr = x + (size_t)rowBase * KDIM;

    float acc[4][2][4];
#pragma unroll
    for (int mi = 0; mi < 4; mi++)
#pragma unroll
        for (int ni = 0; ni < 2; ni++)
#pragma unroll
            for (int j = 0; j < 4; j++) acc[mi][ni][j] = 0.0f;

    const int a_row = wm * 64 + (lid & 15);
    const uint32_t asel = (uint32_t)((lid >> 4) * 16);
    const uint32_t relAH = SM_A_HI + (uint32_t)a_row * 144 + asel;
    const uint32_t relAL = SM_A_LO + (uint32_t)a_row * 144 + asel;
    const int b_row = wn * 16 + ((lid >> 4) << 3) + (lid & 7);
    const uint32_t bsel = (uint32_t)(((lid >> 3) & 1) * 16);
    const uint32_t relBH = SM_B_HI + (uint32_t)b_row * 144 + bsel;
    const uint32_t relBL = SM_B_LO + (uint32_t)b_row * 144 + bsel;

    float4 xbuf[8];
#pragma unroll
    for (int i = 0; i < 8; i++) {
        int l = tid + i * 256;
        xbuf[i] = *reinterpret_cast<const float4*>(xr + (size_t)(l >> 4) * KDIM + (l & 15) * 4);
    }
    stage_chunk(smem, 0, xbuf, tid, 0);
    __syncthreads();

    for (int c = 0; c < NCH; c++) {
        const int buf = c & 1;
        // prefetch next chunk into regs (covered by mma below)
        if (c + 1 < NCH) {
            const int kn = (c + 1) * CHUNK;
#pragma unroll
            for (int i = 0; i < 8; i++) {
                int l = tid + i * 256;
                xbuf[i] = *reinterpret_cast<const float4*>(
                    xr + (size_t)(l >> 4) * KDIM + kn + (l & 15) * 4);
            }
        }
        const uint32_t bb = sb + (uint32_t)buf * BUF_SZ;
#pragma unroll
        for (int kk = 0; kk < 4; kk++) {
            uint32_t bh[4], bl[4];
            ldmx4(bh, bb + relBH + kk * 32);
            ldmx4(bl, bb + relBL + kk * 32);
#pragma unroll
            for (int mi = 0; mi < 4; mi++) {
                uint32_t ah[4], al[4];
                ldmx4(ah, bb + relAH + (uint32_t)(mi * 2304) + kk * 32);
                ldmx4(al, bb + relAL + (uint32_t)(mi * 2304) + kk * 32);
#pragma unroll
                for (int ni = 0; ni < 2; ni++) {
                    mma_bf16(acc[mi][ni], ah, bh[ni * 2], bh[ni * 2 + 1]);
                    mma_bf16(acc[mi][ni], ah, bl[ni * 2], bl[ni * 2 + 1]);
                    mma_bf16(acc[mi][ni], al, bh[ni * 2], bh[ni * 2 + 1]);
                }
            }
        }
        if (c + 1 < NCH) stage_chunk(smem, buf ^ 1, xbuf, tid, (c + 1) * CHUNK);
        __syncthreads();
    }

    // epilogue: stage accs, coalesced write + fused 13-bit hist1
    float* stg = reinterpret_cast<float*>(smem);
#pragma unroll
    for (int mi = 0; mi < 4; mi++) {
        int row = wm * 64 + mi * 16 + (lid >> 2);
        int col = wn * 16 + 2 * (lid & 3);
#pragma unroll
        for (int ni = 0; ni < 2; ni++) {
            int cc = col + ni * 8;
            *reinterpret_cast<float2*>(&stg[row * STG + cc]) =
                make_float2(acc[mi][ni][0], acc[mi][ni][1]);
            *reinterpret_cast<float2*>(&stg[(row + 8) * STG + cc]) =
                make_float2(acc[mi][ni][2], acc[mi][ni][3]);
        }
    }
    __syncthreads();

    const float* nz = noise + (size_t)rowBase * NEXP;
    float* op = out + (size_t)rowBase * NEXP;
#pragma unroll
    for (int j = 0; j < 8; j++) {
        int l = tid + j * 256;
        int r = l >> 4, q = (l & 15) * 4;
        float4 nv = *reinterpret_cast<const float4*>(nz + r * NEXP + q);
        float4 bv = *reinterpret_cast<const float4*>(bias + q);
        float4 o;
        o.x = (stg[r * STG + q + 0] + bv.x) + 0.1f * nv.x;
        o.y = (stg[r * STG + q + 1] + bv.y) + 0.1f * nv.y;
        o.z = (stg[r * STG + q + 2] + bv.z) + 0.1f * nv.z;
        o.w = (stg[r * STG + q + 3] + bv.w) + 0.1f * nv.w;
        *reinterpret_cast<float4*>(op + r * NEXP + q) = o;
        atomicAdd(&g_hist1[((q + 0) << 13) | (f2o(o.x) >> 19)], 1u);
        atomicAdd(&g_hist1[((q + 1) << 13) | (f2o(o.y) >> 19)], 1u);
        atomicAdd(&g_hist1[((q + 2) << 13) | (f2o(o.z) >> 19)], 1u);
        atomicAdd(&g_hist1[((q + 3) << 13) | (f2o(o.w) >> 19)], 1u);
    }
}

// ---------------- launch index 4: locate quantile buckets (tiny scan) --------
__global__ void find_buckets() {
    const int e = blockIdx.x;
    const uint32_t* h = &g_hist1[e << 13];
    const int t = threadIdx.x, lane = t & 31, w = t >> 5;
    uint32_t bins[32];
    uint32_t s = 0;
#pragma unroll
    for (int j = 0; j < 32; j++) { bins[j] = h[t * 32 + j]; s += bins[j]; }
    __shared__ uint32_t wsum[8], woff[8];
    uint32_t ps = warp_iscan(s, lane);
    if (lane == 31) wsum[w] = ps;
    __syncthreads();
    if (t == 0) {
        uint32_t r2 = 0;
        for (int i = 0; i < 8; i++) { woff[i] = r2; r2 += wsum[i]; }
    }
    __syncthreads();
    uint32_t base = woff[w] + ps - s;
    __shared__ uint32_t rbin[2], rrnk[2];
    for (int ri = 0; ri < 2; ri++) {
        uint32_t r = CRANK0 + (uint32_t)ri;
        if (base <= r && r < base + s) {
            uint32_t cum = base;
#pragma unroll
            for (int j = 0; j < 32; j++) {
                if (r < cum + bins[j]) { rbin[ri] = (uint32_t)(t * 32 + j); rrnk[ri] = r - cum; break; }
                cum += bins[j];
            }
        }
    }
    __syncthreads();
    if (t == 0) {
        g_bkt0[e] = rbin[0]; g_rnk0[e] = rrnk[0];
        g_bkt1[e] = rbin[1]; g_rnk1[e] = rrnk[1];
    }
}

// ---------------- launch index 5: collect candidates in quantile bucket ------
__global__ void collect_pass(const float4* __restrict__ lg, int n4) {
    __shared__ uint32_t b0s[NEXP], b1s[NEXP];
    if (threadIdx.x < NEXP) {
        b0s[threadIdx.x] = g_bkt0[threadIdx.x];
        b1s[threadIdx.x] = g_bkt1[threadIdx.x];
    }
    __syncthreads();
    for (int i = blockIdx.x * blockDim.x + threadIdx.x; i < n4;
         i += gridDim.x * blockDim.x) {
        float4 v = lg[i];
        int col = (i * 4) & 63;
        float vals[4] = {v.x, v.y, v.z, v.w};
#pragma unroll
        for (int j = 0; j < 4; j++) {
            uint32_t u = f2o(vals[j]);
            uint32_t hb = u >> 19;
            int c = col + j;
            if (hb == b0s[c]) {
                uint32_t pos = atomicAdd(&g_cnt[c], 1u);
                if (pos < CAP) g_cand[(c << 13) | pos] = u;
            }
            if (b1s[c] != b0s[c] && hb == b1s[c]) atomicMin(&g_minb1[c], u);
        }
    }
}

// ---------------- launch index 6: exact order-stats from candidates ----------
__global__ void select_kernel() {
    const int e = blockIdx.x;
    const int tid = threadIdx.x, lane = tid & 31, w = tid >> 5;
    __shared__ uint32_t hist[4096];
    const uint32_t* cand = &g_cand[e << 13];
    int n = (int)g_cnt[e]; if (n > CAP) n = CAP;
    const uint32_t b0 = g_bkt0[e], b1 = g_bkt1[e];
    const int two = (b0 == b1) ? 1 : 0;
#pragma unroll
    for (int j = 0; j < 16; j++) hist[tid * 16 + j] = 0u;
    __syncthreads();
    for (int i = tid; i < n; i += 256) atomicAdd(&hist[(cand[i] >> 7) & 0xFFFu], 1u);
    __syncthreads();
    uint32_t loc[16];
    uint32_t s = 0;
#pragma unroll
    for (int j = 0; j < 16; j++) { loc[j] = hist[tid * 16 + j]; s += loc[j]; }
    __shared__ uint32_t wsum[8], woff[8];
    uint32_t ps = warp_iscan(s, lane);
    if (lane == 31) wsum[w] = ps;
    __syncthreads();
    if (tid == 0) {
        uint32_t r2 = 0;
        for (int i = 0; i < 8; i++) { woff[i] = r2; r2 += wsum[i]; }
    }
    __syncthreads();
    uint32_t base = woff[w] + ps - s;
    __shared__ uint32_t tb[2], bb[2];
    uint32_t ranks[2] = {g_rnk0[e], g_rnk1[e]};
    for (int ri = 0; ri <= two; ri++) {
        uint32_t r = ranks[ri];
        if (base <= r && r < base + s) {
            uint32_t cum = base;
#pragma unroll
            for (int j = 0; j < 16; j++) {
                if (r < cum + loc[j]) { tb[ri] = (uint32_t)(tid * 16 + j); bb[ri] = cum; break; }
                cum += loc[j];
            }
        }
    }
    __syncthreads();
    __shared__ uint32_t mbuf[2][64];
    __shared__ uint32_t mcnt[2];
    if (tid < 2) mcnt[tid] = 0u;
    __syncthreads();
    for (int i = tid; i < n; i += 256) {
        uint32_t u = cand[i];
        uint32_t bin = (u >> 7) & 0xFFFu;
        for (int ri = 0; ri <= two; ri++) {
            if (bin == tb[ri]) {
                uint32_t k = atomicAdd(&mcnt[ri], 1u);
                if (k < 64) mbuf[ri][k] = u;
            }
        }
    }
    __syncthreads();
    if (tid == 0) {
        uint32_t vals[2];
        for (int ri = 0; ri <= two; ri++) {
            int m = (int)mcnt[ri]; if (m > 64) m = 64;
            for (int i2 = 1; i2 < m; i2++) {
                uint32_t key = mbuf[ri][i2];
                int j2 = i2 - 1;
                while (j2 >= 0 && mbuf[ri][j2] > key) { mbuf[ri][j2 + 1] = mbuf[ri][j2]; j2--; }
                mbuf[ri][j2 + 1] = key;
            }
            vals[ri] = mbuf[ri][ranks[ri] - bb[ri]];
        }
        float s0 = o2f(vals[0]);
        float s1 = two ? o2f(vals[1]) : o2f(g_minb1[e]);
        g_tcol[e] = s0 + 0.25f * (s1 - s0);
    }
}

// ---------------- launch index 7: row masks + softmax ----------------
__global__ __launch_bounds__(256) void row_kernel(float* __restrict__ lg) {
    __shared__ float tc[NEXP];
    const int tid = threadIdx.x;
    if (tid < NEXP) tc[tid] = g_tcol[tid];
    __syncthreads();
    const int lane = tid & 31;
    const int w = tid >> 5;
    const int row = blockIdx.x * 8 + w;

    float v0 = lg[row * NEXP + lane];
    float v1 = lg[row * NEXP + 32 + lane];
    float m0 = (v0 > tc[lane])      ? v0 : HIGH_NEG;
    float m1 = (v1 > tc[lane + 32]) ? v1 : HIGH_NEG;

    float a = fmaxf(m0, m1), b = fminf(m0, m1), c = -3.402823466e38f;
#pragma unroll
    for (int off = 16; off > 0; off >>= 1) {
        float a2 = __shfl_xor_sync(0xffffffffu, a, off);
        float b2 = __shfl_xor_sync(0xffffffffu, b, off);
        float c2 = __shfl_xor_sync(0xffffffffu, c, off);
        float o1, o2, o3;
        if (a >= a2) {
            o1 = a;
            if (b >= a2) { o2 = b;  o3 = fmaxf(c, a2); }
            else         { o2 = a2; o3 = fmaxf(b, b2); }
        } else {
            o1 = a2;
            if (b2 >= a) { o2 = b2; o3 = fmaxf(c2, a); }
            else         { o2 = a;  o3 = fmaxf(b, b2); }
        }
        a = o1; b = o2; c = o3;
    }
    float thr = c + 0.03125f * (b - c);
    float w0 = (m0 > thr) ? m0 : HIGH_NEG;
    float w1 = (m1 > thr) ? m1 : HIGH_NEG;
    float M = (a > thr) ? a : HIGH_NEG;

    float e0 = expf(w0 - M);
    float e1 = expf(w1 - M);
    float ssum = e0 + e1;
#pragma unroll
    for (int off = 16; off > 0; off >>= 1)
        ssum += __shfl_xor_sync(0xffffffffu, ssum, off);

    lg[row * NEXP + lane]      = e0 / ssum;
    lg[row * NEXP + 32 + lane] = e1 / ssum;
}

// ---------------- launch ----------------
extern "C" void kernel_launch(void* const* d_in, const int* in_sizes, int n_in,
                              void* d_out, int out_size) {
    const float *x = nullptr, *noise = nullptr, *W = nullptr, *bias = nullptr;
    for (int i = 0; i < n_in; i++) {
        switch (in_sizes[i]) {
            case NROWS * KDIM: x     = (const float*)d_in[i]; break;
            case NROWS * NEXP: noise = (const float*)d_in[i]; break;
            case NEXP * KDIM:  W     = (const float*)d_in[i]; break;
            case NEXP:         bias  = (const float*)d_in[i]; break;
            default: break;
        }
    }
    float* out = (float*)d_out;
    const int n4 = NROWS * NEXP / 4;

    cudaFuncSetAttribute(gemm_mma, cudaFuncAttributeMaxDynamicSharedMemorySize, SMEM_TOTAL);

    zero_hist1<<<NEXP * NBINS / 4 / 256, 256>>>();          // idx 0
    w_convert<<<NEXP * KDIM / 256, 256>>>(W);               // idx 1
    init_small<<<1, 64>>>();                                // idx 2
    gemm_mma<<<NROWS / BM, 256, SMEM_TOTAL>>>(x, bias, noise, out);  // idx 3 (profiled)
    find_buckets<<<NEXP, 256>>>();                          // idx 4
    collect_pass<<<4096, 256>>>((const float4*)out, n4);    // idx 5
    select_kernel<<<NEXP, 256>>>();                         // idx 6
    row_kernel<<<NROWS / 8, 256>>>(out);                    // idx 7
}

// round 5
// speedup vs baseline: 1.0644x; 1.0644x over previous
#include <cuda_runtime.h>
#include <cuda_bf16.h>
#include <cstdint>

#define NEXP 64
#define KDIM 1024
#define NROWS 131072
#define HIGH_NEG -100000.0f
#define CRANK0 98303u

// ---------------- scratch ----------------
#define NBINS 8192               // 13-bit level-1 histogram
#define CAP 8192                 // candidate capacity per expert
__device__ uint32_t g_hist1[NEXP * NBINS];
__device__ uint32_t g_cand[NEXP * CAP];
__device__ uint32_t g_cnt[NEXP];
__device__ uint32_t g_minb1[NEXP];
__device__ uint32_t g_bkt0[NEXP], g_rnk0[NEXP], g_bkt1[NEXP], g_rnk1[NEXP];
__device__ float    g_tcol[NEXP];
__device__ __nv_bfloat16 g_whi[NEXP * KDIM];
__device__ __nv_bfloat16 g_wlo[NEXP * KDIM];

// ---------------- helpers ----------------
__device__ __forceinline__ uint32_t f2o(float f) {
    uint32_t u = __float_as_uint(f);
    return u ^ ((u & 0x80000000u) ? 0xFFFFFFFFu : 0x80000000u);
}
__device__ __forceinline__ float o2f(uint32_t u) {
    u ^= ((u & 0x80000000u) ? 0x80000000u : 0xFFFFFFFFu);
    return __uint_as_float(u);
}
__device__ __forceinline__ uint32_t smem_u32(const void* p) {
    uint32_t a;
    asm("{ .reg .u64 t; cvta.to.shared.u64 t, %1; cvt.u32.u64 %0, t; }" : "=r"(a) : "l"(p));
    return a;
}
__device__ __forceinline__ void ldmx4(uint32_t* r, uint32_t addr) {
    asm volatile("ldmatrix.sync.aligned.m8n8.x4.shared.b16 {%0,%1,%2,%3}, [%4];"
                 : "=r"(r[0]), "=r"(r[1]), "=r"(r[2]), "=r"(r[3]) : "r"(addr));
}
__device__ __forceinline__ void mma_bf16(float* d, const uint32_t* a,
                                         uint32_t b0, uint32_t b1) {
    asm volatile(
        "mma.sync.aligned.m16n8k16.row.col.f32.bf16.bf16.f32 "
        "{%0,%1,%2,%3}, {%4,%5,%6,%7}, {%8,%9}, {%0,%1,%2,%3};"
        : "+f"(d[0]), "+f"(d[1]), "+f"(d[2]), "+f"(d[3])
        : "r"(a[0]), "r"(a[1]), "r"(a[2]), "r"(a[3]), "r"(b0), "r"(b1));
}
__device__ __forceinline__ uint32_t warp_iscan(uint32_t v, int lane) {
#pragma unroll
    for (int o = 1; o < 32; o <<= 1) {
        uint32_t t = __shfl_up_sync(0xffffffffu, v, o);
        if (lane >= o) v += t;
    }
    return v;
}

// ---------------- zero hist1 ----------------
__global__ void zero_hist1() {
    uint4* a = reinterpret_cast<uint4*>(g_hist1);
    int i = blockIdx.x * blockDim.x + threadIdx.x;
    a[i] = make_uint4(0u, 0u, 0u, 0u);
}

// ---------------- W -> bf16 hi/lo ----------------
__global__ void w_convert(const float* __restrict__ W) {
    int i = blockIdx.x * blockDim.x + threadIdx.x;
    float v = W[i];
    __nv_bfloat16 h = __float2bfloat16(v);
    g_whi[i] = h;
    g_wlo[i] = __float2bfloat16(v - __bfloat162float(h));
}

// ---------------- small inits ----------------
__global__ void init_small() {
    if (threadIdx.x < NEXP) {
        g_cnt[threadIdx.x] = 0u;
        g_minb1[threadIdx.x] = 0xFFFFFFFFu;
    }
}

// ---------------- single-buffer mma GEMM (R3 structure) ----------------------
#define BM 128
#define CHUNK 64
#define NCH (KDIM / CHUNK)
#define SM_A_HI 0
#define SM_A_LO 18432
#define SM_B_HI 36864
#define SM_B_LO 46080
#define SMEM_TOTAL 55296
#define STG 68

__global__ __launch_bounds__(256, 2) void gemm_mma(
    const float* __restrict__ x, const float* __restrict__ bias,
    const float* __restrict__ noise, float* __restrict__ out)
{
    extern __shared__ char smem[];
    const uint32_t sb = smem_u32(smem);
    const int tid = threadIdx.x;
    const int wid = tid >> 5, lid = tid & 31;
    const int wm = wid >> 2, wn = wid & 3;     // warp grid 2 x 4
    const int rowBase = blockIdx.x * BM;
    const float* xr = x + (size_t)rowBase * KDIM;

    float acc[4][2][4];
#pragma unroll
    for (int mi = 0; mi < 4; mi++)
#pragma unroll
        for (int ni = 0; ni < 2; ni++)
#pragma unroll
            for (int j = 0; j < 4; j++) acc[mi][ni][j] = 0.0f;

    const int a_row = wm * 64 + (lid & 15);
    const uint32_t asel = (uint32_t)((lid >> 4) * 16);
    const uint32_t aoffH = sb + SM_A_HI + (uint32_t)a_row * 144 + asel;
    const uint32_t aoffL = sb + SM_A_LO + (uint32_t)a_row * 144 + asel;
    const int b_row = wn * 16 + ((lid >> 4) << 3) + (lid & 7);
    const uint32_t bsel = (uint32_t)(((lid >> 3) & 1) * 16);
    const uint32_t boffH = sb + SM_B_HI + (uint32_t)b_row * 144 + bsel;
    const uint32_t boffL = sb + SM_B_LO + (uint32_t)b_row * 144 + bsel;

    float4 xbuf[8];
#pragma unroll
    for (int i = 0; i < 8; i++) {
        int l = tid + i * 256;
        xbuf[i] = *reinterpret_cast<const float4*>(xr + (size_t)(l >> 4) * KDIM + (l & 15) * 4);
    }

    for (int c = 0; c < NCH; c++) {
        const int kc = c * CHUNK;
        // ---- convert x chunk to hi/lo bf16, store padded (isolated store phase) ----
#pragma unroll
        for (int i = 0; i < 8; i++) {
            int l = tid + i * 256;
            int r = l >> 4, q = l & 15;
            float4 v = xbuf[i];
            uint32_t h01, h23, l01, l23;
            asm("cvt.rn.bf16x2.f32 %0, %1, %2;" : "=r"(h01) : "f"(v.y), "f"(v.x));
            asm("cvt.rn.bf16x2.f32 %0, %1, %2;" : "=r"(h23) : "f"(v.w), "f"(v.z));
            float r0 = v.x - __uint_as_float(h01 << 16);
            float r1 = v.y - __uint_as_float(h01 & 0xFFFF0000u);
            float r2 = v.z - __uint_as_float(h23 << 16);
            float r3 = v.w - __uint_as_float(h23 & 0xFFFF0000u);
            asm("cvt.rn.bf16x2.f32 %0, %1, %2;" : "=r"(l01) : "f"(r1), "f"(r0));
            asm("cvt.rn.bf16x2.f32 %0, %1, %2;" : "=r"(l23) : "f"(r3), "f"(r2));
            uint32_t off = (uint32_t)(r * 144 + q * 8);
            *reinterpret_cast<uint2*>(smem + SM_A_HI + off) = make_uint2(h01, h23);
            *reinterpret_cast<uint2*>(smem + SM_A_LO + off) = make_uint2(l01, l23);
        }
        {
            const uint4* wh = reinterpret_cast<const uint4*>(g_whi);
            const uint4* wl = reinterpret_cast<const uint4*>(g_wlo);
#pragma unroll
            for (int i = 0; i < 2; i++) {
                int l = tid + i * 256;
                int e = l >> 3, q = l & 7;
                uint32_t src = (uint32_t)(e * KDIM + kc) >> 3;
                uint32_t off = (uint32_t)(e * 144 + q * 16);
                *reinterpret_cast<uint4*>(smem + SM_B_HI + off) = wh[src + q];
                *reinterpret_cast<uint4*>(smem + SM_B_LO + off) = wl[src + q];
            }
        }
        __syncthreads();

        // ---- prefetch next chunk (covered by MMA phase) ----
        if (c + 1 < NCH) {
            const int kn = kc + CHUNK;
#pragma unroll
            for (int i = 0; i < 8; i++) {
                int l = tid + i * 256;
                xbuf[i] = *reinterpret_cast<const float4*>(
                    xr + (size_t)(l >> 4) * KDIM + kn + (l & 15) * 4);
            }
        }

        // ---- mma over chunk ----
#pragma unroll
        for (int kk = 0; kk < 4; kk++) {
            uint32_t bh[4], bl[4];
            ldmx4(bh, boffH + kk * 32);
            ldmx4(bl, boffL + kk * 32);
#pragma unroll
            for (int mi = 0; mi < 4; mi++) {
                uint32_t ah[4], al[4];
                ldmx4(ah, aoffH + (uint32_t)(mi * 2304) + kk * 32);
                ldmx4(al, aoffL + (uint32_t)(mi * 2304) + kk * 32);
#pragma unroll
                for (int ni = 0; ni < 2; ni++) {
                    mma_bf16(acc[mi][ni], ah, bh[ni * 2], bh[ni * 2 + 1]);
                    mma_bf16(acc[mi][ni], ah, bl[ni * 2], bl[ni * 2 + 1]);
                    mma_bf16(acc[mi][ni], al, bh[ni * 2], bh[ni * 2 + 1]);
                }
            }
        }
        __syncthreads();
    }

    // ---- epilogue: stage accs, coalesced write + fused 13-bit hist1 ----
    float* stg = reinterpret_cast<float*>(smem);
#pragma unroll
    for (int mi = 0; mi < 4; mi++) {
        int row = wm * 64 + mi * 16 + (lid >> 2);
        int col = wn * 16 + 2 * (lid & 3);
#pragma unroll
        for (int ni = 0; ni < 2; ni++) {
            int cc = col + ni * 8;
            *reinterpret_cast<float2*>(&stg[row * STG + cc]) =
                make_float2(acc[mi][ni][0], acc[mi][ni][1]);
            *reinterpret_cast<float2*>(&stg[(row + 8) * STG + cc]) =
                make_float2(acc[mi][ni][2], acc[mi][ni][3]);
        }
    }
    __syncthreads();

    const float* nz = noise + (size_t)rowBase * NEXP;
    float* op = out + (size_t)rowBase * NEXP;
#pragma unroll
    for (int j = 0; j < 8; j++) {
        int l = tid + j * 256;
        int r = l >> 4, q = (l & 15) * 4;
        float4 nv = *reinterpret_cast<const float4*>(nz + r * NEXP + q);
        float4 bv = *reinterpret_cast<const float4*>(bias + q);
        float4 o;
        o.x = (stg[r * STG + q + 0] + bv.x) + 0.1f * nv.x;
        o.y = (stg[r * STG + q + 1] + bv.y) + 0.1f * nv.y;
        o.z = (stg[r * STG + q + 2] + bv.z) + 0.1f * nv.z;
        o.w = (stg[r * STG + q + 3] + bv.w) + 0.1f * nv.w;
        *reinterpret_cast<float4*>(op + r * NEXP + q) = o;
        atomicAdd(&g_hist1[((q + 0) << 13) | (f2o(o.x) >> 19)], 1u);
        atomicAdd(&g_hist1[((q + 1) << 13) | (f2o(o.y) >> 19)], 1u);
        atomicAdd(&g_hist1[((q + 2) << 13) | (f2o(o.z) >> 19)], 1u);
        atomicAdd(&g_hist1[((q + 3) << 13) | (f2o(o.w) >> 19)], 1u);
    }
}

// ---------------- locate quantile buckets ----------------
__global__ void find_buckets() {
    const int e = blockIdx.x;
    const uint32_t* h = &g_hist1[e << 13];
    const int t = threadIdx.x, lane = t & 31, w = t >> 5;
    uint32_t bins[32];
    uint32_t s = 0;
#pragma unroll
    for (int j = 0; j < 32; j++) { bins[j] = h[t * 32 + j]; s += bins[j]; }
    __shared__ uint32_t wsum[8], woff[8];
    uint32_t ps = warp_iscan(s, lane);
    if (lane == 31) wsum[w] = ps;
    __syncthreads();
    if (t == 0) {
        uint32_t r2 = 0;
        for (int i = 0; i < 8; i++) { woff[i] = r2; r2 += wsum[i]; }
    }
    __syncthreads();
    uint32_t base = woff[w] + ps - s;
    __shared__ uint32_t rbin[2], rrnk[2];
    for (int ri = 0; ri < 2; ri++) {
        uint32_t r = CRANK0 + (uint32_t)ri;
        if (base <= r && r < base + s) {
            uint32_t cum = base;
#pragma unroll
            for (int j = 0; j < 32; j++) {
                if (r < cum + bins[j]) { rbin[ri] = (uint32_t)(t * 32 + j); rrnk[ri] = r - cum; break; }
                cum += bins[j];
            }
        }
    }
    __syncthreads();
    if (t == 0) {
        g_bkt0[e] = rbin[0]; g_rnk0[e] = rrnk[0];
        g_bkt1[e] = rbin[1]; g_rnk1[e] = rrnk[1];
    }
}

// ---------------- collect candidates ----------------
__global__ void collect_pass(const float4* __restrict__ lg, int n4) {
    __shared__ uint32_t b0s[NEXP], b1s[NEXP];
    if (threadIdx.x < NEXP) {
        b0s[threadIdx.x] = g_bkt0[threadIdx.x];
        b1s[threadIdx.x] = g_bkt1[threadIdx.x];
    }
    __syncthreads();
    for (int i = blockIdx.x * blockDim.x + threadIdx.x; i < n4;
         i += gridDim.x * blockDim.x) {
        float4 v = lg[i];
        int col = (i * 4) & 63;
        float vals[4] = {v.x, v.y, v.z, v.w};
#pragma unroll
        for (int j = 0; j < 4; j++) {
            uint32_t u = f2o(vals[j]);
            uint32_t hb = u >> 19;
            int c = col + j;
            if (hb == b0s[c]) {
                uint32_t pos = atomicAdd(&g_cnt[c], 1u);
                if (pos < CAP) g_cand[(c << 13) | pos] = u;
            }
            if (b1s[c] != b0s[c] && hb == b1s[c]) atomicMin(&g_minb1[c], u);
        }
    }
}

// ---------------- exact order-stats from candidates ----------------
__global__ void select_kernel() {
    const int e = blockIdx.x;
    const int tid = threadIdx.x, lane = tid & 31, w = tid >> 5;
    __shared__ uint32_t hist[4096];
    const uint32_t* cand = &g_cand[e << 13];
    int n = (int)g_cnt[e]; if (n > CAP) n = CAP;
    const uint32_t b0 = g_bkt0[e], b1 = g_bkt1[e];
    const int two = (b0 == b1) ? 1 : 0;
#pragma unroll
    for (int j = 0; j < 16; j++) hist[tid * 16 + j] = 0u;
    __syncthreads();
    for (int i = tid; i < n; i += 256) atomicAdd(&hist[(cand[i] >> 7) & 0xFFFu], 1u);
    __syncthreads();
    uint32_t loc[16];
    uint32_t s = 0;
#pragma unroll
    for (int j = 0; j < 16; j++) { loc[j] = hist[tid * 16 + j]; s += loc[j]; }
    __shared__ uint32_t wsum[8], woff[8];
    uint32_t ps = warp_iscan(s, lane);
    if (lane == 31) wsum[w] = ps;
    __syncthreads();
    if (tid == 0) {
        uint32_t r2 = 0;
        for (int i = 0; i < 8; i++) { woff[i] = r2; r2 += wsum[i]; }
    }
    __syncthreads();
    uint32_t base = woff[w] + ps - s;
    __shared__ uint32_t tb[2], bb[2];
    uint32_t ranks[2] = {g_rnk0[e], g_rnk1[e]};
    for (int ri = 0; ri <= two; ri++) {
        uint32_t r = ranks[ri];
        if (base <= r && r < base + s) {
            uint32_t cum = base;
#pragma unroll
            for (int j = 0; j < 16; j++) {
                if (r < cum + loc[j]) { tb[ri] = (uint32_t)(tid * 16 + j); bb[ri] = cum; break; }
                cum += loc[j];
            }
        }
    }
    __syncthreads();
    __shared__ uint32_t mbuf[2][64];
    __shared__ uint32_t mcnt[2];
    if (tid < 2) mcnt[tid] = 0u;
    __syncthreads();
    for (int i = tid; i < n; i += 256) {
        uint32_t u = cand[i];
        uint32_t bin = (u >> 7) & 0xFFFu;
        for (int ri = 0; ri <= two; ri++) {
            if (bin == tb[ri]) {
                uint32_t k = atomicAdd(&mcnt[ri], 1u);
                if (k < 64) mbuf[ri][k] = u;
            }
        }
    }
    __syncthreads();
    if (tid == 0) {
        uint32_t vals[2];
        for (int ri = 0; ri <= two; ri++) {
            int m = (int)mcnt[ri]; if (m > 64) m = 64;
            for (int i2 = 1; i2 < m; i2++) {
                uint32_t key = mbuf[ri][i2];
                int j2 = i2 - 1;
                while (j2 >= 0 && mbuf[ri][j2] > key) { mbuf[ri][j2 + 1] = mbuf[ri][j2]; j2--; }
                mbuf[ri][j2 + 1] = key;
            }
            vals[ri] = mbuf[ri][ranks[ri] - bb[ri]];
        }
        float s0 = o2f(vals[0]);
        float s1 = two ? o2f(vals[1]) : o2f(g_minb1[e]);
        g_tcol[e] = s0 + 0.25f * (s1 - s0);
    }
}

// ---------------- row masks + softmax ----------------
__global__ __launch_bounds__(256) void row_kernel(float* __restrict__ lg) {
    __shared__ float tc[NEXP];
    const int tid = threadIdx.x;
    if (tid < NEXP) tc[tid] = g_tcol[tid];
    __syncthreads();
    const int lane = tid & 31;
    const int w = tid >> 5;
    const int row = blockIdx.x * 8 + w;

    float v0 = lg[row * NEXP + lane];
    float v1 = lg[row * NEXP + 32 + lane];
    float m0 = (v0 > tc[lane])      ? v0 : HIGH_NEG;
    float m1 = (v1 > tc[lane + 32]) ? v1 : HIGH_NEG;

    float a = fmaxf(m0, m1), b = fminf(m0, m1), c = -3.402823466e38f;
#pragma unroll
    for (int off = 16; off > 0; off >>= 1) {
        float a2 = __shfl_xor_sync(0xffffffffu, a, off);
        float b2 = __shfl_xor_sync(0xffffffffu, b, off);
        float c2 = __shfl_xor_sync(0xffffffffu, c, off);
        float o1, o2, o3;
        if (a >= a2) {
            o1 = a;
            if (b >= a2) { o2 = b;  o3 = fmaxf(c, a2); }
            else         { o2 = a2; o3 = fmaxf(b, b2); }
        } else {
            o1 = a2;
            if (b2 >= a) { o2 = b2; o3 = fmaxf(c2, a); }
            else         { o2 = a;  o3 = fmaxf(b, b2); }
        }
        a = o1; b = o2; c = o3;
    }
    float thr = c + 0.03125f * (b - c);
    float w0 = (m0 > thr) ? m0 : HIGH_NEG;
    float w1 = (m1 > thr) ? m1 : HIGH_NEG;
    float M = (a > thr) ? a : HIGH_NEG;

    float e0 = expf(w0 - M);
    float e1 = expf(w1 - M);
    float ssum = e0 + e1;
#pragma unroll
    for (int off = 16; off > 0; off >>= 1)
        ssum += __shfl_xor_sync(0xffffffffu, ssum, off);

    lg[row * NEXP + lane]      = e0 / ssum;
    lg[row * NEXP + 32 + lane] = e1 / ssum;
}

// ---------------- launch ----------------
extern "C" void kernel_launch(void* const* d_in, const int* in_sizes, int n_in,
                              void* d_out, int out_size) {
    const float *x = nullptr, *noise = nullptr, *W = nullptr, *bias = nullptr;
    for (int i = 0; i < n_in; i++) {
        switch (in_sizes[i]) {
            case NROWS * KDIM: x     = (const float*)d_in[i]; break;
            case NROWS * NEXP: noise = (const float*)d_in[i]; break;
            case NEXP * KDIM:  W     = (const float*)d_in[i]; break;
            case NEXP:         bias  = (const float*)d_in[i]; break;
            default: break;
        }
    }
    float* out = (float*)d_out;
    const int n4 = NROWS * NEXP / 4;

    cudaFuncSetAttribute(gemm_mma, cudaFuncAttributeMaxDynamicSharedMemorySize, SMEM_TOTAL);

    zero_hist1<<<NEXP * NBINS / 4 / 256, 256>>>();          // idx 0
    w_convert<<<NEXP * KDIM / 256, 256>>>(W);               // idx 1
    init_small<<<1, 64>>>();                                // idx 2
    gemm_mma<<<NROWS / BM, 256, SMEM_TOTAL>>>(x, bias, noise, out);  // idx 3
    find_buckets<<<NEXP, 256>>>();                          // idx 4
    collect_pass<<<4096, 256>>>((const float4*)out, n4);    // idx 5
    select_kernel<<<NEXP, 256>>>();                         // idx 6
    row_kernel<<<NROWS / 8, 256>>>(out);                    // idx 7
}